// round 15
// baseline (speedup 1.0000x reference)
#include <cuda_runtime.h>
#include <cuda_bf16.h>
#include <math.h>
#include <stdint.h>

// ---------------- scratch (no allocations allowed) ----------------
__device__ float g_Q[2048 * 4096];
__device__ float g_K[2048 * 1024];
__device__ float g_V[2048 * 1024];

// bf16 hi/lo operands, row-major [K,N] (for fallback mma.sync path)
__device__ __nv_bfloat16 g_hsh[2048 * 4096], g_hsl[2048 * 4096];
__device__ __nv_bfloat16 g_WqhKN[4096 * 4096], g_WqlKN[4096 * 4096];
__device__ __nv_bfloat16 g_WkhKN[4096 * 1024], g_WklKN[4096 * 1024];
__device__ __nv_bfloat16 g_WvhKN[4096 * 1024], g_WvlKN[4096 * 1024];
__device__ __nv_bfloat16 g_WohKN[4096 * 4096], g_WolKN[4096 * 4096];
// transposed [N,K] copies (tcgen05 B operand, K-major)
__device__ __nv_bfloat16 g_WqhT[4096 * 4096], g_WqlT[4096 * 4096];
__device__ __nv_bfloat16 g_WkhT[1024 * 4096], g_WklT[1024 * 4096];
__device__ __nv_bfloat16 g_WvhT[1024 * 4096], g_WvlT[1024 * 4096];
__device__ __nv_bfloat16 g_WohT[4096 * 4096], g_WolT[4096 * 4096];
__device__ __nv_bfloat16 g_Ahh[2048 * 4096], g_Ahl[2048 * 4096];   // attn out hi/lo

// ---------------- arch-feature guard ----------------
#if defined(__CUDA_ARCH_FEAT_SM103_ALL) || defined(__CUDA_ARCH_FEAT_SM100_ALL)
#define USE_TCGEN05 1
#else
#define USE_TCGEN05 0
#endif

// ---------------- common helpers ----------------
#define SWZ(x) ((x) ^ (((x) >> 3) & 0x70))

__device__ __forceinline__ uint32_t smem_u32(const void* p) {
    return (uint32_t)__cvta_generic_to_shared(p);
}
__device__ __forceinline__ uint32_t elect_one() {
    uint32_t pred;
    asm volatile("{\n\t.reg .pred p;\n\telect.sync _|p, 0xFFFFFFFF;\n\t"
                 "selp.b32 %0, 1, 0, p;\n\t}" : "=r"(pred));
    return pred;
}
__device__ __forceinline__ void mbar_init(uint32_t mbar, uint32_t cnt) {
    asm volatile("mbarrier.init.shared.b64 [%0], %1;" :: "r"(mbar), "r"(cnt) : "memory");
}
__device__ __forceinline__ void mbar_wait(uint32_t mbar, uint32_t parity) {
    asm volatile("{\n\t.reg .pred P1;\n\t"
                 "LAB_WAIT_%=:\n\t"
                 "mbarrier.try_wait.parity.acquire.cta.shared::cta.b64 P1, [%0], %1, 0x989680;\n\t"
                 "@P1 bra LAB_DONE_%=;\n\t"
                 "bra LAB_WAIT_%=;\n\t"
                 "LAB_DONE_%=:\n\t}" :: "r"(mbar), "r"(parity) : "memory");
}
static constexpr uint64_t DESC_BASE_SW128 =
    (uint64_t(2) << 61) | (uint64_t(1) << 46) | (uint64_t(64) << 32) | (uint64_t(1) << 16);
__device__ __forceinline__ uint64_t make_desc(uint32_t addr) {
    return DESC_BASE_SW128 | ((uint64_t)(addr >> 4) & 0x3FFF);
}
// idesc kind::f16: f32 acc | bf16 a | bf16 b | N=128 | M=128  (cross-checked vs 0x8080490)
static constexpr uint32_t TC_IDESC =
    (1u << 4) | (1u << 7) | (1u << 10) | ((128 / 8) << 17) | ((128 / 16) << 24);

// legacy path helpers
__device__ __forceinline__ void ldsm_x4(uint32_t* r, uint32_t addr) {
    asm volatile("ldmatrix.sync.aligned.m8n8.x4.shared.b16 {%0,%1,%2,%3}, [%4];\n"
                 : "=r"(r[0]), "=r"(r[1]), "=r"(r[2]), "=r"(r[3]) : "r"(addr));
}
__device__ __forceinline__ void ldsm_x2_t(uint32_t* r, uint32_t addr) {
    asm volatile("ldmatrix.sync.aligned.m8n8.x2.trans.shared.b16 {%0,%1}, [%2];\n"
                 : "=r"(r[0]), "=r"(r[1]) : "r"(addr));
}
__device__ __forceinline__ void mma_bf16(float* d, const uint32_t* a, const uint32_t* b) {
    asm volatile("mma.sync.aligned.m16n8k16.row.col.f32.bf16.bf16.f32 "
                 "{%0,%1,%2,%3}, {%4,%5,%6,%7}, {%8,%9}, {%0,%1,%2,%3};\n"
                 : "+f"(d[0]), "+f"(d[1]), "+f"(d[2]), "+f"(d[3])
                 : "r"(a[0]), "r"(a[1]), "r"(a[2]), "r"(a[3]), "r"(b[0]), "r"(b[1]));
}
__device__ __forceinline__ void cp_async16(uint32_t dst, const void* src) {
    asm volatile("cp.async.cg.shared.global [%0], [%1], 16;\n" :: "r"(dst), "l"(src));
}
__device__ __forceinline__ void cp_commit() { asm volatile("cp.async.commit_group;\n"); }
__device__ __forceinline__ void cp_wait0()  { asm volatile("cp.async.wait_group 0;\n"); }

// ---------------- fp32 -> hi/lo bf16 split (row-major) ----------------
__global__ void split_fp32(const float* __restrict__ X,
                           __nv_bfloat16* __restrict__ H,
                           __nv_bfloat16* __restrict__ L, int n4) {
    int i = blockIdx.x * 256 + threadIdx.x;
    if (i >= n4) return;
    float4 v = ((const float4*)X)[i];
    float vv[4] = {v.x, v.y, v.z, v.w};
    __nv_bfloat16 h[4], l[4];
#pragma unroll
    for (int j = 0; j < 4; j++) {
        h[j] = __float2bfloat16(vv[j]);
        l[j] = __float2bfloat16(vv[j] - __bfloat162float(h[j]));
    }
    ((uint2*)H)[i] = *(uint2*)h;
    ((uint2*)L)[i] = *(uint2*)l;
}

// ---------------- fp32 [K,N] -> transposed hi/lo bf16 [N,K] ----------------
__global__ void transpose_split(const float* __restrict__ X,
                                __nv_bfloat16* __restrict__ H,
                                __nv_bfloat16* __restrict__ L, int Kd, int Nd) {
    __shared__ float tile[32][33];
    int bn = blockIdx.x * 32;
    int bk = blockIdx.y * 32;
    int tx = threadIdx.x;
    int ty = threadIdx.y;
#pragma unroll
    for (int i = 0; i < 32; i += 8)
        tile[ty + i][tx] = X[(size_t)(bk + ty + i) * Nd + bn + tx];
    __syncthreads();
#pragma unroll
    for (int i = 0; i < 32; i += 8) {
        float v = tile[tx][ty + i];
        __nv_bfloat16 h = __float2bfloat16(v);
        __nv_bfloat16 l = __float2bfloat16(v - __bfloat162float(h));
        size_t o = (size_t)(bn + ty + i) * Kd + bk + tx;
        H[o] = h;
        L[o] = l;
    }
}

// ---------------- dual-path GEMM: C[M,N] = A[M,K] @ B ----------------
// A hi/lo row-major [M,K]. Bkn hi/lo row-major [K,N] (legacy path);
// Bnk hi/lo row-major [N,K] (tcgen05 SS path, K-major B).
// grid (N/128, M/128), 256 threads, 66560B dynamic smem.
__global__ __launch_bounds__(256) void gemm_dual(
    const __nv_bfloat16* __restrict__ Ah,   const __nv_bfloat16* __restrict__ Al,
    const __nv_bfloat16* __restrict__ BknH, const __nv_bfloat16* __restrict__ BknL,
    const __nv_bfloat16* __restrict__ BnkH, const __nv_bfloat16* __restrict__ BnkL,
    float* __restrict__ C, int M, int N, int K) {
    extern __shared__ char smem[];
    const int t    = threadIdx.x;
    const int wid  = t >> 5;
    const int lane = t & 31;
    const int bm = blockIdx.y * 128;
    const int bn = blockIdx.x * 128;

#if USE_TCGEN05
    // ===================== tcgen05 path (sm_103a/sm_100a cubin) =====================
    const uint32_t sb = smem_u32(smem);
    const uint32_t OF_AH = 1024, OF_AL = 1024 + 16384,
                   OF_BH = 1024 + 32768, OF_BL = 1024 + 49152;

    if (wid == 0) {
        asm volatile("tcgen05.alloc.cta_group::1.sync.aligned.shared::cta.b32 [%0], %1;"
                     :: "r"(sb), "r"(128u) : "memory");
    }
    if (t == 0) mbar_init(sb + 8, 1);
    __syncthreads();
    uint32_t tmem;
    asm volatile("ld.shared.b32 %0, [%1];" : "=r"(tmem) : "r"(sb));

    const uint64_t dAh = make_desc(sb + OF_AH);
    const uint64_t dAl = make_desc(sb + OF_AL);
    const uint64_t dBh = make_desc(sb + OF_BH);
    const uint64_t dBl = make_desc(sb + OF_BL);

    uint32_t phase = 0;
    const int NT = K >> 6;                 // 64-element K chunks (128B SW128 rows)
    for (int it = 0; it < NT; it++) {
        const int k0 = it << 6;
#pragma unroll
        for (int i = 0; i < 4; i++) {      // 4 tiles x (128 rows x 128B); 16B per slot
            int c = t + i * 256;
            int row = c >> 3;
            int g = c & 7;
            uint32_t off = SWZ((uint32_t)(row * 128 + g * 16));
            size_t ga = (size_t)(bm + row) * K + k0 + g * 8;
            size_t gb = (size_t)(bn + row) * K + k0 + g * 8;
            *(uint4*)(smem + OF_AH + off) = *(const uint4*)(Ah + ga);
            *(uint4*)(smem + OF_AL + off) = *(const uint4*)(Al + ga);
            *(uint4*)(smem + OF_BH + off) = *(const uint4*)(BnkH + gb);
            *(uint4*)(smem + OF_BL + off) = *(const uint4*)(BnkL + gb);
        }
        __syncthreads();
        if (wid == 0) {
            asm volatile("fence.proxy.async.shared::cta;" ::: "memory");
            if (elect_one()) {
#pragma unroll
                for (int kc = 0; kc < 4; kc++) {          // 4 x K16 inside the 128B atom
                    uint32_t en0 = (it == 0 && kc == 0) ? 0u : 1u;
                    asm volatile("{\n\t.reg .pred p;\n\tsetp.ne.u32 p, %4, 0;\n\t"
                                 "tcgen05.mma.cta_group::1.kind::f16 [%0], %1, %2, %3, "
                                 "{%5, %5, %5, %5}, p;\n\t}"
                                 :: "r"(tmem), "l"(dAh + kc * 2), "l"(dBh + kc * 2),
                                    "r"(TC_IDESC), "r"(en0), "r"(0u) : "memory");
                    asm volatile("{\n\t.reg .pred p;\n\tsetp.ne.u32 p, %4, 0;\n\t"
                                 "tcgen05.mma.cta_group::1.kind::f16 [%0], %1, %2, %3, "
                                 "{%5, %5, %5, %5}, p;\n\t}"
                                 :: "r"(tmem), "l"(dAh + kc * 2), "l"(dBl + kc * 2),
                                    "r"(TC_IDESC), "r"(1u), "r"(0u) : "memory");
                    asm volatile("{\n\t.reg .pred p;\n\tsetp.ne.u32 p, %4, 0;\n\t"
                                 "tcgen05.mma.cta_group::1.kind::f16 [%0], %1, %2, %3, "
                                 "{%5, %5, %5, %5}, p;\n\t}"
                                 :: "r"(tmem), "l"(dAl + kc * 2), "l"(dBh + kc * 2),
                                    "r"(TC_IDESC), "r"(1u), "r"(0u) : "memory");
                }
                asm volatile(
                    "tcgen05.commit.cta_group::1.mbarrier::arrive::one.shared::cluster.b64 [%0];"
                    :: "r"(sb + 8) : "memory");
            }
        }
        mbar_wait(sb + 8, phase);
        phase ^= 1;
        __syncthreads();
    }

    asm volatile("tcgen05.fence::after_thread_sync;" ::: "memory");

    // epilogue: warps 0-3 read their subpartitions (rows wid*32+lane), all 128 cols
    if (wid < 4) {
        for (int cb = 0; cb < 128; cb += 32) {
            uint32_t d[32];
            asm volatile(
                "tcgen05.ld.sync.aligned.32x32b.x32.b32 "
                "{%0,%1,%2,%3,%4,%5,%6,%7,%8,%9,%10,%11,%12,%13,%14,%15,"
                "%16,%17,%18,%19,%20,%21,%22,%23,%24,%25,%26,%27,%28,%29,%30,%31}, [%32];"
                : "=r"(d[0]), "=r"(d[1]), "=r"(d[2]), "=r"(d[3]), "=r"(d[4]), "=r"(d[5]),
                  "=r"(d[6]), "=r"(d[7]), "=r"(d[8]), "=r"(d[9]), "=r"(d[10]), "=r"(d[11]),
                  "=r"(d[12]), "=r"(d[13]), "=r"(d[14]), "=r"(d[15]), "=r"(d[16]), "=r"(d[17]),
                  "=r"(d[18]), "=r"(d[19]), "=r"(d[20]), "=r"(d[21]), "=r"(d[22]), "=r"(d[23]),
                  "=r"(d[24]), "=r"(d[25]), "=r"(d[26]), "=r"(d[27]), "=r"(d[28]), "=r"(d[29]),
                  "=r"(d[30]), "=r"(d[31])
                : "r"(tmem + cb));
            asm volatile("tcgen05.wait::ld.sync.aligned;" ::: "memory");
            int m = bm + wid * 32 + lane;
            float4* crow = (float4*)(C + (size_t)m * N + bn + cb);
#pragma unroll
            for (int c = 0; c < 32; c += 4)
                crow[c >> 2] = make_float4(__uint_as_float(d[c]), __uint_as_float(d[c + 1]),
                                           __uint_as_float(d[c + 2]), __uint_as_float(d[c + 3]));
        }
    }

    asm volatile("tcgen05.fence::before_thread_sync;" ::: "memory");
    __syncthreads();
    if (wid == 0) {
        asm volatile("tcgen05.dealloc.cta_group::1.sync.aligned.b32 %0, %1;"
                     :: "r"(tmem), "r"(128u));
    }
#else
    // ===================== legacy mma.sync path (proven R13 body) =====================
    __shared__ __align__(16) __nv_bfloat16 sA[2][2][128][24];
    __shared__ __align__(16) __nv_bfloat16 sB[2][2][16][136];

    const int warp_m = wid & 1;
    const int warp_n = wid >> 1;

    const int arow = t >> 1;
    const int akc  = (t & 1) * 8;
    const int brow = t >> 4;
    const int bnc  = (t & 15) * 8;

    auto load_tile = [&](int it, int st) {
        int k0 = it * 16;
        size_t sa = (size_t)(bm + arow) * K + k0 + akc;
        cp_async16(smem_u32(&sA[st][0][arow][akc]), Ah + sa);
        cp_async16(smem_u32(&sA[st][1][arow][akc]), Al + sa);
        size_t sbi = (size_t)(k0 + brow) * N + bn + bnc;
        cp_async16(smem_u32(&sB[st][0][brow][bnc]), BknH + sbi);
        cp_async16(smem_u32(&sB[st][1][brow][bnc]), BknL + sbi);
    };

    float acc[4][4][4];
#pragma unroll
    for (int mi = 0; mi < 4; mi++)
#pragma unroll
        for (int ni = 0; ni < 4; ni++)
#pragma unroll
            for (int r = 0; r < 4; r++) acc[mi][ni][r] = 0.f;

    const int NT = K / 16;
    load_tile(0, 0);
    cp_commit();

    for (int it = 0; it < NT; it++) {
        cp_wait0();
        __syncthreads();
        const int b = it & 1;
        if (it + 1 < NT) { load_tile(it + 1, b ^ 1); cp_commit(); }

        uint32_t ah[4][4], al[4][4];
#pragma unroll
        for (int mi = 0; mi < 4; mi++) {
            int row = warp_m * 64 + mi * 16 + (lane & 15);
            int col = (lane >> 4) << 3;
            ldsm_x4(ah[mi], smem_u32(&sA[b][0][row][col]));
            ldsm_x4(al[mi], smem_u32(&sA[b][1][row][col]));
        }
        uint32_t bh[4][2], bl[4][2];
#pragma unroll
        for (int ni = 0; ni < 4; ni++) {
            int row = lane & 15;
            int col = warp_n * 32 + ni * 8;
            ldsm_x2_t(bh[ni], smem_u32(&sB[b][0][row][col]));
            ldsm_x2_t(bl[ni], smem_u32(&sB[b][1][row][col]));
        }
#pragma unroll
        for (int mi = 0; mi < 4; mi++)
#pragma unroll
            for (int ni = 0; ni < 4; ni++) {
                mma_bf16(acc[mi][ni], ah[mi], bh[ni]);
                mma_bf16(acc[mi][ni], ah[mi], bl[ni]);
                mma_bf16(acc[mi][ni], al[mi], bh[ni]);
            }
        __syncthreads();
    }

    const int gid = lane >> 2;
    const int tid = lane & 3;
#pragma unroll
    for (int mi = 0; mi < 4; mi++)
#pragma unroll
        for (int ni = 0; ni < 4; ni++) {
            int row = bm + warp_m * 64 + mi * 16 + gid;
            int col = bn + warp_n * 32 + ni * 8 + tid * 2;
            C[(size_t)row * N + col]           = acc[mi][ni][0];
            C[(size_t)row * N + col + 1]       = acc[mi][ni][1];
            C[(size_t)(row + 8) * N + col]     = acc[mi][ni][2];
            C[(size_t)(row + 8) * N + col + 1] = acc[mi][ni][3];
        }
#endif
}

// ---------------- RoPE (in-place) — UNCHANGED (proven) ----------------
__global__ void rope_naive(float* __restrict__ X, const int* __restrict__ pos_ids, int nh) {
    int idx = blockIdx.x * 256 + threadIdx.x;
    int total = 2048 * nh * 64;
    if (idx >= total) return;
    int i = idx % 64;
    int h = (idx / 64) % nh;
    int s = idx / (64 * nh);
    const float LN10000 = 9.210340371976184f;
    float inv = __expf(-((float)(2 * i) / 128.0f) * LN10000);
    float ang = (float)pos_ids[s] * inv;
    float c = cosf(ang);
    float sn = sinf(ang);
    float* row = X + (size_t)s * (nh * 128) + h * 128;
    float x1 = row[i];
    float x2 = row[i + 64];
    row[i]      = x1 * c - x2 * sn;
    row[i + 64] = x2 * c + x1 * sn;
}

// ---------------- attention — UNCHANGED (proven) ----------------
__global__ __launch_bounds__(256) void attn_q4(const float* __restrict__ Q,
                                               const float* __restrict__ K,
                                               const float* __restrict__ V,
                                               __nv_bfloat16* __restrict__ Oh,
                                               __nv_bfloat16* __restrict__ Ol) {
    __shared__ float sc[4][2048];
    __shared__ float qs[4][128];
    __shared__ float red[256];

    const int qb = blockIdx.x;
    const int h  = blockIdx.y;
    const int kh = h >> 2;
    const int t  = threadIdx.x;
    const int q0 = qb * 4;
    const int qmax = q0 + 3;

    const float scale = 0.08838834764831845f;

    for (int i = t; i < 512; i += 256) {
        int r = i >> 7;
        int d = i & 127;
        qs[r][d] = Q[(size_t)(q0 + r) * 4096 + h * 128 + d];
    }
    __syncthreads();

    const int r  = t & 3;
    const int ks = t >> 2;
    float mx = -INFINITY;
    for (int k = ks; k <= qmax; k += 64) {
        const float* krow = K + (size_t)k * 1024 + kh * 128;
        float s = 0.f;
#pragma unroll 8
        for (int d4 = 0; d4 < 128; d4 += 4) {
            float4 kv = *(const float4*)(krow + d4);
            float4 qv = *(const float4*)&qs[r][d4];
            s += qv.x * kv.x + qv.y * kv.y + qv.z * kv.z + qv.w * kv.w;
        }
        s *= scale;
        if (k > q0 + r) s = -1e30f;
        sc[r][k] = s;
        mx = fmaxf(mx, s);
    }

    red[t] = mx;
    __syncthreads();
    for (int off = 128; off >= 4; off >>= 1) {
        if (t < off) red[t] = fmaxf(red[t], red[t + off]);
        __syncthreads();
    }
    float mrow = red[r];
    __syncthreads();

    float sum = 0.f;
    for (int k = ks; k <= qmax; k += 64) {
        float p = __expf(sc[r][k] - mrow);
        sc[r][k] = p;
        sum += p;
    }
    red[t] = sum;
    __syncthreads();
    for (int off = 128; off >= 4; off >>= 1) {
        if (t < off) red[t] += red[t + off];
        __syncthreads();
    }

    const int d   = t & 127;
    const int rp0 = (t >> 7) * 2;
    const int rp1 = rp0 + 1;
    const float* vcol = V + (size_t)kh * 128 + d;

    float acc0 = 0.f, acc1 = 0.f;
    for (int k = 0; k <= qmax; k++) {
        float v = vcol[(size_t)k * 1024];
        acc0 += sc[rp0][k] * v;
        acc1 += sc[rp1][k] * v;
    }

    float o0 = acc0 / red[rp0];
    float o1 = acc1 / red[rp1];
    size_t i0 = (size_t)(q0 + rp0) * 4096 + h * 128 + d;
    size_t i1 = (size_t)(q0 + rp1) * 4096 + h * 128 + d;
    __nv_bfloat16 h0 = __float2bfloat16(o0);
    __nv_bfloat16 h1 = __float2bfloat16(o1);
    Oh[i0] = h0;  Ol[i0] = __float2bfloat16(o0 - __bfloat162float(h0));
    Oh[i1] = h1;  Ol[i1] = __float2bfloat16(o1 - __bfloat162float(h1));
}

// ---------------- launch ----------------
extern "C" void kernel_launch(void* const* d_in, const int* in_sizes, int n_in,
                              void* d_out, int out_size) {
    int i16[2] = {-1, -1}, n16 = 0;
    int i4[2]  = {-1, -1}, n4  = 0;
    int iHS = -1, iPOS = -1;
    for (int i = 0; i < 6; i++) {
        int s = in_sizes[i];
        if (s == 16777216)      { if (n16 < 2) i16[n16++] = i; }
        else if (s == 4194304)  { if (n4  < 2) i4[n4++]   = i; }
        else if (s == 8388608)  iHS = i;
        else                    iPOS = i;
    }
    int iWq, iWo;
    if (i16[1] == i16[0] + 1) { iWo = i16[0]; iWq = i16[1]; }
    else                      { iWq = i16[0]; iWo = i16[1]; }
    const int iWk = i4[0];
    const int iWv = i4[1];

    const float* hs  = (const float*)d_in[iHS];
    const int*   pos = (const int*)d_in[iPOS];
    const float* Wq  = (const float*)d_in[iWq];
    const float* Wk  = (const float*)d_in[iWk];
    const float* Wv  = (const float*)d_in[iWv];
    const float* Wo  = (const float*)d_in[iWo];
    float* out = (float*)d_out;

    float *Q, *K, *V;
    cudaGetSymbolAddress((void**)&Q, g_Q);
    cudaGetSymbolAddress((void**)&K, g_K);
    cudaGetSymbolAddress((void**)&V, g_V);

    __nv_bfloat16 *hsh, *hsl, *Ahh, *Ahl;
    __nv_bfloat16 *WqhKN, *WqlKN, *WkhKN, *WklKN, *WvhKN, *WvlKN, *WohKN, *WolKN;
    __nv_bfloat16 *WqhT, *WqlT, *WkhT, *WklT, *WvhT, *WvlT, *WohT, *WolT;
    cudaGetSymbolAddress((void**)&hsh, g_hsh);     cudaGetSymbolAddress((void**)&hsl, g_hsl);
    cudaGetSymbolAddress((void**)&Ahh, g_Ahh);     cudaGetSymbolAddress((void**)&Ahl, g_Ahl);
    cudaGetSymbolAddress((void**)&WqhKN, g_WqhKN); cudaGetSymbolAddress((void**)&WqlKN, g_WqlKN);
    cudaGetSymbolAddress((void**)&WkhKN, g_WkhKN); cudaGetSymbolAddress((void**)&WklKN, g_WklKN);
    cudaGetSymbolAddress((void**)&WvhKN, g_WvhKN); cudaGetSymbolAddress((void**)&WvlKN, g_WvlKN);
    cudaGetSymbolAddress((void**)&WohKN, g_WohKN); cudaGetSymbolAddress((void**)&WolKN, g_WolKN);
    cudaGetSymbolAddress((void**)&WqhT, g_WqhT);   cudaGetSymbolAddress((void**)&WqlT, g_WqlT);
    cudaGetSymbolAddress((void**)&WkhT, g_WkhT);   cudaGetSymbolAddress((void**)&WklT, g_WklT);
    cudaGetSymbolAddress((void**)&WvhT, g_WvhT);   cudaGetSymbolAddress((void**)&WvlT, g_WvlT);
    cudaGetSymbolAddress((void**)&WohT, g_WohT);   cudaGetSymbolAddress((void**)&WolT, g_WolT);

    const int SM_BYTES = 1024 + 65536;
    cudaFuncSetAttribute(gemm_dual, cudaFuncAttributeMaxDynamicSharedMemorySize, SM_BYTES);

    // ---- operand prep: row-major splits + transposed splits ----
    {
        int n;
        n = 2048 * 4096 / 4; split_fp32<<<(n + 255) / 256, 256>>>(hs, hsh, hsl, n);
        n = 4096 * 4096 / 4; split_fp32<<<(n + 255) / 256, 256>>>(Wq, WqhKN, WqlKN, n);
        n = 4096 * 1024 / 4; split_fp32<<<(n + 255) / 256, 256>>>(Wk, WkhKN, WklKN, n);
        n = 4096 * 1024 / 4; split_fp32<<<(n + 255) / 256, 256>>>(Wv, WvhKN, WvlKN, n);
        n = 4096 * 4096 / 4; split_fp32<<<(n + 255) / 256, 256>>>(Wo, WohKN, WolKN, n);
        dim3 blk(32, 8);
        transpose_split<<<dim3(4096 / 32, 4096 / 32), blk>>>(Wq, WqhT, WqlT, 4096, 4096);
        transpose_split<<<dim3(1024 / 32, 4096 / 32), blk>>>(Wk, WkhT, WklT, 4096, 1024);
        transpose_split<<<dim3(1024 / 32, 4096 / 32), blk>>>(Wv, WvhT, WvlT, 4096, 1024);
        transpose_split<<<dim3(4096 / 32, 4096 / 32), blk>>>(Wo, WohT, WolT, 4096, 4096);
    }

    // QKV projections
    gemm_dual<<<dim3(32, 16), 256, SM_BYTES>>>(hsh, hsl, WqhKN, WqlKN, WqhT, WqlT,
                                               Q, 2048, 4096, 4096);
    gemm_dual<<<dim3(8, 16), 256, SM_BYTES>>>(hsh, hsl, WkhKN, WklKN, WkhT, WklT,
                                              K, 2048, 1024, 4096);
    gemm_dual<<<dim3(8, 16), 256, SM_BYTES>>>(hsh, hsl, WvhKN, WvlKN, WvhT, WvlT,
                                              V, 2048, 1024, 4096);

    // RoPE
    {
        int totq = 2048 * 32 * 64;
        rope_naive<<<(totq + 255) / 256, 256>>>(Q, pos, 32);
        int totk = 2048 * 8 * 64;
        rope_naive<<<(totk + 255) / 256, 256>>>(K, pos, 8);
    }

    // Attention
    {
        dim3 ga(512, 32);
        attn_q4<<<ga, 256>>>(Q, K, V, Ahh, Ahl);
    }

    // Output projection
    gemm_dual<<<dim3(32, 16), 256, SM_BYTES>>>(Ahh, Ahl, WohKN, WolKN, WohT, WolT,
                                               out, 2048, 4096, 4096);
}